// round 2
// baseline (speedup 1.0000x reference)
#include <cuda_runtime.h>
#include <math.h>

#define NB 148
#define NT 256

__device__ double g_bce;
__device__ double g_hinge;
__device__ unsigned int g_done;   // zero-init; last block resets each launch

__device__ __forceinline__ float read_margin(const void* p) {
    // margin is a python int scalar; hedge across int32/int64/float32 encodings.
    int iv = *(const int*)p;
    if (iv >= -1000000 && iv <= 1000000) return (float)iv;
    return *(const float*)p;
}

__global__ void __launch_bounds__(NT)
fused_kernel(const float* __restrict__ preds,
             const float* __restrict__ labels,
             const float* __restrict__ logits,
             const float* __restrict__ targets,
             const float* __restrict__ pos_weight,
             const void* __restrict__ margin_ptr,
             float* __restrict__ out, int n)
{
    __shared__ float s_pos[8192];       // all positives' (m - pred), any order
    __shared__ float s_neg[256];        // this block's slice negatives (preds)
    __shared__ int   s_np, s_nn;
    __shared__ float s_rh[NT / 32];
    __shared__ float s_rb[NT / 32];

    const int tid  = threadIdx.x;
    const int lane = tid & 31;
    const float m  = read_margin(margin_ptr);

    // this block's slice of ORIGINAL indices (partitions negatives consistently)
    const int chunk = (n + NB - 1) / NB;
    const int s0 = (int)blockIdx.x * chunk;
    const int s1 = min(s0 + chunk, n);

    if (tid == 0) { s_np = 0; s_nn = 0; }
    __syncthreads();

    // ---- compaction: full-array positives + own-slice negatives ----
    for (int i0 = 0; i0 < n; i0 += NT) {
        int i = i0 + tid;
        bool inr = i < n;
        float p = inr ? preds[i]  : 0.f;
        float l = inr ? labels[i] : 0.f;
        bool isPos = inr && (l > 0.5f);
        bool isNegS = inr && !(l > 0.5f) && (i >= s0) && (i < s1);

        unsigned bal = __ballot_sync(0xffffffffu, isPos);
        int base = 0;
        if (lane == 0 && bal) base = atomicAdd(&s_np, __popc(bal));
        base = __shfl_sync(0xffffffffu, base, 0);
        if (isPos) s_pos[base + __popc(bal & ((1u << lane) - 1u))] = m - p;

        bal = __ballot_sync(0xffffffffu, isNegS);
        if (lane == 0 && bal) base = atomicAdd(&s_nn, __popc(bal));
        base = __shfl_sync(0xffffffffu, base, 0);
        if (isNegS) s_neg[base + __popc(bal & ((1u << lane) - 1u))] = p;
    }

    // ---- BCE over own slice ----
    float bce = 0.f;
    {
        float pw = pos_weight[0];
        for (int i = s0 + tid; i < s1; i += NT) {
            float x  = logits[i];
            float t  = targets[i];
            float mv = fmaxf(-x, 0.f);
            float lw = 1.f + (pw - 1.f) * t;
            bce += (1.f - t) * x + lw * (logf(expf(-mv) + expf(-x - mv)) + mv);
        }
    }
    __syncthreads();

    const int n1 = s_np;
    const int nn = s_nn;

    // ---- cross-product hinge: all positives x own-slice negatives ----
    float acc = 0.f;
    for (int base = tid * 8; base < n1; base += NT * 8) {
        float a[8];
        #pragma unroll
        for (int k = 0; k < 8; k++)
            a[k] = (base + k < n1) ? s_pos[base + k] : -1e30f;
        for (int j = 0; j < nn; j++) {
            float q = s_neg[j];
            #pragma unroll
            for (int k = 0; k < 8; k++)
                acc += fmaxf(a[k] + q, 0.f);
        }
    }

    // ---- block reduce (hinge + bce) ----
    #pragma unroll
    for (int o = 16; o; o >>= 1) {
        acc += __shfl_down_sync(0xffffffffu, acc, o);
        bce += __shfl_down_sync(0xffffffffu, bce, o);
    }
    int wid = tid >> 5;
    if (lane == 0) { s_rh[wid] = acc; s_rb[wid] = bce; }
    __syncthreads();
    if (tid == 0) {
        float sh = 0.f, sb = 0.f;
        #pragma unroll
        for (int w = 0; w < NT / 32; w++) { sh += s_rh[w]; sb += s_rb[w]; }
        atomicAdd(&g_hinge, (double)sh);
        atomicAdd(&g_bce,   (double)sb);

        __threadfence();
        unsigned ticket = atomicAdd(&g_done, 1u);
        if (ticket == (unsigned)gridDim.x - 1u) {
            // last block: finalize + reset for next graph replay
            double hinge = g_hinge;
            double bces  = g_bce;
            long long ln1 = n1, ln0 = (long long)n - n1;
            double c_same = 0.5 * (double)(ln1 * (ln1 - 1)) +
                            0.5 * (double)(ln0 * (ln0 - 1));
            double md = (double)m;
            double same = (md > 0.0) ? c_same * md : 0.0;
            out[0] = (float)((same + hinge) / (double)n);
            out[1] = (float)(bces / (double)n);
            g_hinge = 0.0;
            g_bce   = 0.0;
            __threadfence();
            g_done  = 0u;
        }
    }
}

extern "C" void kernel_launch(void* const* d_in, const int* in_sizes, int n_in,
                              void* d_out, int out_size) {
    const float* preds      = (const float*)d_in[0];
    const float* labels     = (const float*)d_in[1];
    const float* logits     = (const float*)d_in[2];
    const float* targets    = (const float*)d_in[3];
    const float* pos_weight = (const float*)d_in[4];
    const void*  margin     = d_in[5];
    float* out = (float*)d_out;
    int n = in_sizes[0];

    fused_kernel<<<NB, NT>>>(preds, labels, logits, targets,
                             pos_weight, margin, out, n);
}

// round 4
// speedup vs baseline: 1.6178x; 1.6178x over previous
#include <cuda_runtime.h>
#include <math.h>

#define NB   148
#define NT   256
#define NW   (NT / 32)
#define RMAX 8          // 8192 / (NT*4)

__device__ double g_bce;
__device__ double g_hinge;
__device__ unsigned int g_done;   // zero-init; last block resets each launch

__device__ __forceinline__ float read_margin(const void* p) {
    // margin is a python int scalar; hedge across int32/int64/float32 encodings.
    int iv = *(const int*)p;
    if (iv >= -1000000 && iv <= 1000000) return (float)iv;
    return *(const float*)p;
}

__global__ void __launch_bounds__(NT)
fused_kernel(const float* __restrict__ preds,
             const float* __restrict__ labels,
             const float* __restrict__ logits,
             const float* __restrict__ targets,
             const float* __restrict__ pos_weight,
             const void* __restrict__ margin_ptr,
             float* __restrict__ out, int n)
{
    __shared__ float s_pos[8192];     // all positives' (m - pred), tightly packed
    __shared__ float s_neg[64];       // this block's slice negatives (preds)
    __shared__ int   s_wcnt[NW];
    __shared__ int   s_wpref[NW];
    __shared__ int   s_n1, s_nn;
    __shared__ float s_rh[NW], s_rb[NW];

    const int tid  = threadIdx.x;
    const int lane = tid & 31;
    const int wid  = tid >> 5;
    const float m  = read_margin(margin_ptr);

    const int chunk = (n + NB - 1) / NB;
    const int s0 = (int)blockIdx.x * chunk;
    const int s1 = min(s0 + chunk, n);

    if (tid == 0) s_nn = 0;

    // ---- Phase A: vectorized load + predicate mask (no smem, no atomics) ----
    const float4* p4 = (const float4*)preds;
    const float4* l4 = (const float4*)labels;
    const int nf4 = n >> 2;
    float4 pv[RMAX];
    unsigned mask = 0;
    #pragma unroll
    for (int r = 0; r < RMAX; r++) {
        int f = r * NT + tid;
        if (f < nf4) {
            pv[r] = p4[f];
            float4 lv = l4[f];
            if (lv.x > 0.5f) mask |= 1u << (r * 4 + 0);
            if (lv.y > 0.5f) mask |= 1u << (r * 4 + 1);
            if (lv.z > 0.5f) mask |= 1u << (r * 4 + 2);
            if (lv.w > 0.5f) mask |= 1u << (r * 4 + 3);
        }
    }
    int cnt = __popc(mask);
    #pragma unroll
    for (int o = 16; o; o >>= 1) cnt += __shfl_down_sync(0xffffffffu, cnt, o);
    if (lane == 0) s_wcnt[wid] = cnt;
    __syncthreads();

    if (tid == 0) {
        int acc = 0;
        #pragma unroll
        for (int w = 0; w < NW; w++) { s_wpref[w] = acc; acc += s_wcnt[w]; }
        s_n1 = acc;
    }
    __syncthreads();

    // ---- Phase B: exact-offset scatter from registers (ballot rank, no atomics) ----
    {
        int off = s_wpref[wid];
        #pragma unroll
        for (int r = 0; r < RMAX; r++) {
            #pragma unroll
            for (int c = 0; c < 4; c++) {
                bool bit = (mask >> (r * 4 + c)) & 1u;
                unsigned bal = __ballot_sync(0xffffffffu, bit);
                if (bit) {
                    float v = (c == 0) ? pv[r].x : (c == 1) ? pv[r].y
                            : (c == 2) ? pv[r].z : pv[r].w;
                    s_pos[off + __popc(bal & ((1u << lane) - 1u))] = m - v;
                }
                off += __popc(bal);
            }
        }
    }

    // ---- Phase C: own-slice negative compaction (warps 0,1) + BCE ----
    if (wid < 2) {
        int i = s0 + tid;
        bool isNeg = (i < s1) && !(labels[i] > 0.5f);
        float p = isNeg ? preds[i] : 0.f;
        unsigned bal = __ballot_sync(0xffffffffu, isNeg);
        int base = 0;
        if (lane == 0 && bal) base = atomicAdd(&s_nn, __popc(bal));
        base = __shfl_sync(0xffffffffu, base, 0);
        if (isNeg) s_neg[base + __popc(bal & ((1u << lane) - 1u))] = p;
    }

    float bce = 0.f;
    {
        float pw = pos_weight[0];
        for (int i = s0 + tid; i < s1; i += NT) {
            float x  = logits[i];
            float t  = targets[i];
            float mv = fmaxf(-x, 0.f);
            float lw = 1.f + (pw - 1.f) * t;
            bce += (1.f - t) * x + lw * (logf(expf(-mv) + expf(-x - mv)) + mv);
        }
    }
    __syncthreads();

    const int n1 = s_n1;
    const int nn = s_nn;

    // ---- Phase D: cross-product hinge: all positives x own-slice negatives ----
    float acc0 = 0.f, acc1 = 0.f;
    for (int base = tid * 8; base < n1; base += NT * 8) {
        float a[8];
        #pragma unroll
        for (int k = 0; k < 8; k++)
            a[k] = (base + k < n1) ? s_pos[base + k] : -1e30f;
        #pragma unroll 4
        for (int j = 0; j < nn; j++) {
            float q = s_neg[j];
            acc0 += fmaxf(a[0] + q, 0.f);
            acc0 += fmaxf(a[1] + q, 0.f);
            acc0 += fmaxf(a[2] + q, 0.f);
            acc0 += fmaxf(a[3] + q, 0.f);
            acc1 += fmaxf(a[4] + q, 0.f);
            acc1 += fmaxf(a[5] + q, 0.f);
            acc1 += fmaxf(a[6] + q, 0.f);
            acc1 += fmaxf(a[7] + q, 0.f);
        }
    }
    float acc = acc0 + acc1;

    // ---- block reduce + global accumulate + last-block finalize ----
    #pragma unroll
    for (int o = 16; o; o >>= 1) {
        acc += __shfl_down_sync(0xffffffffu, acc, o);
        bce += __shfl_down_sync(0xffffffffu, bce, o);
    }
    if (lane == 0) { s_rh[wid] = acc; s_rb[wid] = bce; }
    __syncthreads();
    if (tid == 0) {
        float sh = 0.f, sb = 0.f;
        #pragma unroll
        for (int w = 0; w < NW; w++) { sh += s_rh[w]; sb += s_rb[w]; }
        atomicAdd(&g_hinge, (double)sh);
        atomicAdd(&g_bce,   (double)sb);

        __threadfence();
        unsigned ticket = atomicAdd(&g_done, 1u);
        if (ticket == (unsigned)gridDim.x - 1u) {
            double hinge = g_hinge;
            double bces  = g_bce;
            long long ln1 = n1, ln0 = (long long)n - n1;
            double c_same = 0.5 * (double)(ln1 * (ln1 - 1)) +
                            0.5 * (double)(ln0 * (ln0 - 1));
            double md = (double)m;
            double same = (md > 0.0) ? c_same * md : 0.0;
            out[0] = (float)((same + hinge) / (double)n);
            out[1] = (float)(bces / (double)n);
            g_hinge = 0.0;
            g_bce   = 0.0;
            __threadfence();
            g_done  = 0u;
        }
    }
}

extern "C" void kernel_launch(void* const* d_in, const int* in_sizes, int n_in,
                              void* d_out, int out_size) {
    const float* preds      = (const float*)d_in[0];
    const float* labels     = (const float*)d_in[1];
    const float* logits     = (const float*)d_in[2];
    const float* targets    = (const float*)d_in[3];
    const float* pos_weight = (const float*)d_in[4];
    const void*  margin     = d_in[5];
    float* out = (float*)d_out;
    int n = in_sizes[0];

    fused_kernel<<<NB, NT>>>(preds, labels, logits, targets,
                             pos_weight, margin, out, n);
}

// round 8
// speedup vs baseline: 1.7843x; 1.1029x over previous
#include <cuda_runtime.h>
#include <math.h>

#define NCHUNK 148        // negative-slice tiles
#define NQ     4          // positive-quarter tiles
#define NT     256
#define NW     (NT / 32)
#define RQ     2          // float4 loads per thread per quarter (2048/4/256)
#define QCAP   2304       // >= quarter size worst case

__device__ double g_bce;
__device__ double g_hinge;
__device__ int    g_n1;
__device__ unsigned int g_done;   // zero-init; last block resets each launch

__device__ __forceinline__ float read_margin(const void* p) {
    // margin is a python int scalar; hedge across int32/int64/float32 encodings.
    int iv = *(const int*)p;
    if (iv >= -1000000 && iv <= 1000000) return (float)iv;
    return *(const float*)p;
}

__global__ void __launch_bounds__(NT)
fused_kernel(const float* __restrict__ preds,
             const float* __restrict__ labels,
             const float* __restrict__ logits,
             const float* __restrict__ targets,
             const float* __restrict__ pos_weight,
             const void* __restrict__ margin_ptr,
             float* __restrict__ out, int n)
{
    __shared__ float s_pos[QCAP];   // this quarter's positives (m - pred), packed
    __shared__ float s_neg[64];     // this chunk's negatives (preds), packed
    __shared__ int   s_wcnt[NW], s_wpref[NW];
    __shared__ int   s_n1, s_nn;
    __shared__ float s_rh[NW], s_rb[NW];

    const int tid  = threadIdx.x;
    const int lane = tid & 31;
    const int wid  = tid >> 5;
    const float m  = read_margin(margin_ptr);

    const int cid = (int)blockIdx.x;            // negative chunk id [0,148)
    const int qid = (int)blockIdx.y;            // positive quarter id [0,4)

    const int chunk = (n + NCHUNK - 1) / NCHUNK;     // 56
    const int c0 = cid * chunk;
    const int c1 = min(c0 + chunk, n);

    const int qsize = (n + NQ - 1) / NQ;             // 2048
    const int q0 = qid * qsize;
    const int q1 = min(q0 + qsize, n);
    const int nf4 = (q1 - q0) >> 2;                  // 512 (n divisible by 4)

    // ---- Phase A: load this quarter's preds/labels, build predicate mask ----
    const float4* p4 = (const float4*)(preds  + q0);
    const float4* l4 = (const float4*)(labels + q0);
    float4 pv[RQ];
    unsigned mask = 0;
    #pragma unroll
    for (int r = 0; r < RQ; r++) {
        int f = r * NT + tid;
        if (f < nf4) {
            pv[r] = p4[f];
            float4 lv = l4[f];
            if (lv.x > 0.5f) mask |= 1u << (r * 4 + 0);
            if (lv.y > 0.5f) mask |= 1u << (r * 4 + 1);
            if (lv.z > 0.5f) mask |= 1u << (r * 4 + 2);
            if (lv.w > 0.5f) mask |= 1u << (r * 4 + 3);
        }
    }
    int cnt = __popc(mask);
    #pragma unroll
    for (int o = 16; o; o >>= 1) cnt += __shfl_down_sync(0xffffffffu, cnt, o);
    if (lane == 0) s_wcnt[wid] = cnt;
    __syncthreads();

    if (tid == 0) {
        int acc = 0;
        #pragma unroll
        for (int w = 0; w < NW; w++) { s_wpref[w] = acc; acc += s_wcnt[w]; }
        s_n1 = acc;
    }
    __syncthreads();

    // ---- Phase B: exact-offset scatter from registers (ballot rank) ----
    {
        int off = s_wpref[wid];
        #pragma unroll
        for (int r = 0; r < RQ; r++) {
            #pragma unroll
            for (int c = 0; c < 4; c++) {
                bool bit = (mask >> (r * 4 + c)) & 1u;
                unsigned bal = __ballot_sync(0xffffffffu, bit);
                if (bit) {
                    float v = (c == 0) ? pv[r].x : (c == 1) ? pv[r].y
                            : (c == 2) ? pv[r].z : pv[r].w;
                    s_pos[off + __popc(bal & ((1u << lane) - 1u))] = m - v;
                }
                off += __popc(bal);
            }
        }
    }

    // ---- Phase C: own-chunk negative compaction (warp 0 only, no atomics) ----
    if (wid == 0) {
        int nn_local = 0;
        #pragma unroll
        for (int r = 0; r < 2; r++) {
            int i = c0 + r * 32 + lane;
            bool isNeg = (i < c1) && !(labels[i] > 0.5f);
            float p = isNeg ? preds[i] : 0.f;
            unsigned bal = __ballot_sync(0xffffffffu, isNeg);
            if (isNeg) s_neg[nn_local + __popc(bal & ((1u << lane) - 1u))] = p;
            nn_local += __popc(bal);
        }
        if (lane == 0) s_nn = nn_local;
    }

    // ---- BCE over own chunk (quarter-0 blocks only, avoids 4x duplication) ----
    float bce = 0.f;
    if (qid == 0) {
        float pw = pos_weight[0];
        for (int i = c0 + tid; i < c1; i += NT) {
            float x  = logits[i];
            float t  = targets[i];
            float mv = fmaxf(-x, 0.f);
            float lw = 1.f + (pw - 1.f) * t;
            bce += (1.f - t) * x + lw * (logf(expf(-mv) + expf(-x - mv)) + mv);
        }
    }
    __syncthreads();

    const int n1q = s_n1;
    const int nn  = s_nn;

    // ---- Phase D: quarter-positives x chunk-negatives hinge ----
    float acc0 = 0.f, acc1 = 0.f;
    for (int base = tid * 4; base < n1q; base += NT * 4) {
        float a0 = (base + 0 < n1q) ? s_pos[base + 0] : -1e30f;
        float a1 = (base + 1 < n1q) ? s_pos[base + 1] : -1e30f;
        float a2 = (base + 2 < n1q) ? s_pos[base + 2] : -1e30f;
        float a3 = (base + 3 < n1q) ? s_pos[base + 3] : -1e30f;
        #pragma unroll 4
        for (int j = 0; j < nn; j++) {
            float q = s_neg[j];
            acc0 += fmaxf(a0 + q, 0.f);
            acc0 += fmaxf(a1 + q, 0.f);
            acc1 += fmaxf(a2 + q, 0.f);
            acc1 += fmaxf(a3 + q, 0.f);
        }
    }
    float acc = acc0 + acc1;

    // ---- block reduce + global accumulate + last-block finalize ----
    #pragma unroll
    for (int o = 16; o; o >>= 1) {
        acc += __shfl_down_sync(0xffffffffu, acc, o);
        bce += __shfl_down_sync(0xffffffffu, bce, o);
    }
    if (lane == 0) { s_rh[wid] = acc; s_rb[wid] = bce; }
    __syncthreads();
    if (tid == 0) {
        float sh = 0.f, sb = 0.f;
        #pragma unroll
        for (int w = 0; w < NW; w++) { sh += s_rh[w]; sb += s_rb[w]; }
        atomicAdd(&g_hinge, (double)sh);
        if (qid == 0) atomicAdd(&g_bce, (double)sb);
        if (cid == 0) atomicAdd(&g_n1, n1q);     // total positives, once per quarter

        __threadfence();
        unsigned ticket = atomicAdd(&g_done, 1u);
        if (ticket == (unsigned)(gridDim.x * gridDim.y) - 1u) {
            double hinge = g_hinge;
            double bces  = g_bce;
            long long ln1 = g_n1, ln0 = (long long)n - ln1;
            double c_same = 0.5 * (double)(ln1 * (ln1 - 1)) +
                            0.5 * (double)(ln0 * (ln0 - 1));
            double md = (double)m;
            double same = (md > 0.0) ? c_same * md : 0.0;
            out[0] = (float)((same + hinge) / (double)n);
            out[1] = (float)(bces / (double)n);
            g_hinge = 0.0;
            g_bce   = 0.0;
            g_n1    = 0;
            __threadfence();
            g_done  = 0u;
        }
    }
}

extern "C" void kernel_launch(void* const* d_in, const int* in_sizes, int n_in,
                              void* d_out, int out_size) {
    const float* preds      = (const float*)d_in[0];
    const float* labels     = (const float*)d_in[1];
    const float* logits     = (const float*)d_in[2];
    const float* targets    = (const float*)d_in[3];
    const float* pos_weight = (const float*)d_in[4];
    const void*  margin     = d_in[5];
    float* out = (float*)d_out;
    int n = in_sizes[0];

    dim3 grid(NCHUNK, NQ);
    fused_kernel<<<grid, NT>>>(preds, labels, logits, targets,
                               pos_weight, margin, out, n);
}